// round 7
// baseline (speedup 1.0000x reference)
#include <cuda_runtime.h>
#include <cuda_fp16.h>
#include <cstdint>

#define BATCH 4
#define NNODE 20000
#define DN 64
#define DM 128
#define NE 160000
#define NL 2
#define ROWS (BATCH*NNODE)   // 80000
#define NEDGE_TOT (3*NE)     // 480000

// ---------------- scratch (device globals) ----------------------------------
__device__ float   g_H[(size_t)ROWS * DM];            // 41 MB
__device__ __half2 g_Hh[(size_t)ROWS * 64];           // 20.5 MB fp16 mirror
__device__ float   g_G[(size_t)ROWS * 3 * DM];        // 123 MB (tf32-rounded)
__device__ float   g_Cterm[(size_t)NL * NNODE * DM];  // 20.5 MB
__device__ float2  g_Wpre[(size_t)NL * 24576];        // B-fragment images
__device__ float   g_S0[(size_t)NNODE * 16];
__device__ float   g_S1[(size_t)NNODE * 16];
__device__ float   g_cnt[(size_t)NNODE * 4];
__device__ int     g_deg[NNODE];
__device__ int     g_off[NNODE + 1];
__device__ int     g_cursor[NNODE];
__device__ int2    g_entries[NEDGE_TOT];

__device__ __forceinline__ float to_tf32(float x) {
    uint32_t u;
    asm("cvt.rna.tf32.f32 %0, %1;" : "=r"(u) : "f"(x));
    return __uint_as_float(u);
}

__device__ __forceinline__ void cp16(void* dst, const void* src) {
    uint32_t d = (uint32_t)__cvta_generic_to_shared(dst);
    asm volatile("cp.async.cg.shared.global [%0], [%1], 16;" :: "r"(d), "l"(src));
}
__device__ __forceinline__ void cp_commit() {
    asm volatile("cp.async.commit_group;");
}
__device__ __forceinline__ void cp_wait0() {
    asm volatile("cp.async.wait_group 0;");
}

// ---------------- fp32 SGEMM (inproj; also emits fp16 mirror) ----------------
__global__ __launch_bounds__(256)
void sgemm128(const float* __restrict__ A, const float* __restrict__ W,
              const float* __restrict__ bias, float* __restrict__ C,
              __half2* __restrict__ Ch,
              int M, int K, int ldc, int coff)
{
    __shared__ float As[2][8][128];
    __shared__ float Bs[2][8][128];
    const int bm  = blockIdx.x * 128;
    const int tid = threadIdx.x;
    const int tx  = tid & 15;
    const int ty  = tid >> 4;

    float acc[8][8];
#pragma unroll
    for (int i = 0; i < 8; i++)
#pragma unroll
        for (int j = 0; j < 8; j++) acc[i][j] = 0.f;

    const int lm  = tid >> 1;
    const int lk4 = (tid & 1) * 4;
    const int lkB = tid >> 5;
    const int lnB = (tid & 31) * 4;
    const bool arow_ok = (bm + lm) < M;
    const float* Aptr = A + (size_t)(bm + lm) * K + lk4;

    float4 av = make_float4(0.f, 0.f, 0.f, 0.f);
    if (arow_ok) av = *reinterpret_cast<const float4*>(Aptr);
    float4 bv = *reinterpret_cast<const float4*>(W + (size_t)lkB * 128 + lnB);
    As[0][lk4 + 0][lm] = av.x; As[0][lk4 + 1][lm] = av.y;
    As[0][lk4 + 2][lm] = av.z; As[0][lk4 + 3][lm] = av.w;
    *reinterpret_cast<float4*>(&Bs[0][lkB][lnB]) = bv;
    __syncthreads();

    int cur = 0;
    for (int k0 = 8; k0 < K; k0 += 8) {
        av = make_float4(0.f, 0.f, 0.f, 0.f);
        if (arow_ok) av = *reinterpret_cast<const float4*>(Aptr + k0);
        bv = *reinterpret_cast<const float4*>(W + (size_t)(k0 + lkB) * 128 + lnB);
#pragma unroll
        for (int kk = 0; kk < 8; kk++) {
            float a[8], b[8];
#pragma unroll
            for (int i = 0; i < 8; i++) a[i] = As[cur][kk][ty * 8 + i];
#pragma unroll
            for (int j = 0; j < 8; j++) b[j] = Bs[cur][kk][tx * 8 + j];
#pragma unroll
            for (int i = 0; i < 8; i++)
#pragma unroll
                for (int j = 0; j < 8; j++)
                    acc[i][j] = fmaf(a[i], b[j], acc[i][j]);
        }
        int nxt = cur ^ 1;
        As[nxt][lk4 + 0][lm] = av.x; As[nxt][lk4 + 1][lm] = av.y;
        As[nxt][lk4 + 2][lm] = av.z; As[nxt][lk4 + 3][lm] = av.w;
        *reinterpret_cast<float4*>(&Bs[nxt][lkB][lnB]) = bv;
        __syncthreads();
        cur = nxt;
    }
#pragma unroll
    for (int kk = 0; kk < 8; kk++) {
        float a[8], b[8];
#pragma unroll
        for (int i = 0; i < 8; i++) a[i] = As[cur][kk][ty * 8 + i];
#pragma unroll
        for (int j = 0; j < 8; j++) b[j] = Bs[cur][kk][tx * 8 + j];
#pragma unroll
        for (int i = 0; i < 8; i++)
#pragma unroll
            for (int j = 0; j < 8; j++)
                acc[i][j] = fmaf(a[i], b[j], acc[i][j]);
    }
#pragma unroll
    for (int i = 0; i < 8; i++) {
        int gm = bm + ty * 8 + i;
        if (gm < M) {
#pragma unroll
            for (int j = 0; j < 8; j += 4) {
                int n = tx * 8 + j;
                float4 o;
                o.x = acc[i][j + 0] + bias[n + 0];
                o.y = acc[i][j + 1] + bias[n + 1];
                o.z = acc[i][j + 2] + bias[n + 2];
                o.w = acc[i][j + 3] + bias[n + 3];
                *reinterpret_cast<float4*>(C + (size_t)gm * ldc + coff + n) = o;
                if (Ch) {
                    __half2 h0 = __floats2half2_rn(o.x, o.y);
                    __half2 h1 = __floats2half2_rn(o.z, o.w);
                    *reinterpret_cast<uint2*>(Ch + (size_t)gm * 64 + n / 2) =
                        make_uint2(*reinterpret_cast<uint32_t*>(&h0),
                                   *reinterpret_cast<uint32_t*>(&h1));
                }
            }
        }
    }
}

// ---------------- W pre-conversion to B-fragment smem image -----------------
__global__ void prep_w_kernel(const float* __restrict__ node_W,
                              float2* __restrict__ Wpre)
{
    int idx = blockIdx.x * blockDim.x + threadIdx.x;
    if (idx >= NL * 24576) return;
    int l   = idx / 24576;
    int r   = idx % 24576;
    int ch  = r >> 10;
    int ks  = (r >> 9) & 1;
    int n   = (r >> 2) & 127;
    int kl  = r & 3;
    int k   = ch * 16 + ks * 8 + kl;
    const float* W = node_W + (size_t)l * 3 * DM * DM;   // [384][128]
    float lo = to_tf32(W[(size_t)k * 128 + n]);
    float hi = to_tf32(W[(size_t)(k + 4) * 128 + n]);
    Wpre[idx] = make_float2(lo, hi);
}

// ---------------- tf32 tensor-core fused GEMM + Cterm + relu + H + LN -------
__global__ __launch_bounds__(256)
void gemm_ln_tf32(const float* __restrict__ G, const float2* __restrict__ Wpre,
                  const float* __restrict__ H, const float* __restrict__ Ct,
                  const float* __restrict__ gamma, const float* __restrict__ beta,
                  float* __restrict__ out, __half2* __restrict__ outh)
{
    __shared__ union SmemU {
        char  raw[2][18432];
        float C[64][132];
    } sm;

    const int tid  = threadIdx.x;
    const int bm   = blockIdx.x * 128;
    const int w    = tid >> 5;
    const int lane = tid & 31;
    const int ly   = lane >> 2;
    const int lx   = lane & 3;

    const int arow = tid >> 1;
    const int aseg = (tid & 1) * 2;
    const int bks  = tid >> 7;
    const int bn   = tid & 127;
    const float* Arow = G + (size_t)(bm + arow) * 384 + aseg * 4;
    const char*  Wp   = reinterpret_cast<const char*>(Wpre) + ((size_t)bks * 128 + bn) * 32;

    float acc[16][4];
#pragma unroll
    for (int nt = 0; nt < 16; nt++)
#pragma unroll
        for (int j = 0; j < 4; j++) acc[nt][j] = 0.f;

    auto stage = [&](int s, int ch) {
        char* A = sm.raw[s];
        char* B = sm.raw[s] + 10240;
        cp16(A + arow * 80 + aseg * 16,      Arow + ch * 16);
        cp16(A + arow * 80 + aseg * 16 + 16, Arow + ch * 16 + 4);
        const char* src = Wp + (size_t)ch * 8192;
        cp16(B + bks * 4096 + bn * 32,      src);
        cp16(B + bks * 4096 + bn * 32 + 16, src + 16);
    };

    stage(0, 0);
    cp_commit();

    int buf = 0;
#pragma unroll 1
    for (int ch = 0; ch < 24; ch++) {
        cp_wait0();
        __syncthreads();
        if (ch + 1 < 24) { stage(buf ^ 1, ch + 1); cp_commit(); }

        const float* A = reinterpret_cast<const float*>(sm.raw[buf]);
        const char*  B = sm.raw[buf] + 10240;
#pragma unroll
        for (int ks = 0; ks < 2; ks++) {
            const int kk = ks * 8;
            uint32_t a0 = __float_as_uint(A[(w * 16 + ly) * 20 + kk + lx]);
            uint32_t a1 = __float_as_uint(A[(w * 16 + ly + 8) * 20 + kk + lx]);
            uint32_t a2 = __float_as_uint(A[(w * 16 + ly) * 20 + kk + lx + 4]);
            uint32_t a3 = __float_as_uint(A[(w * 16 + ly + 8) * 20 + kk + lx + 4]);
#pragma unroll
            for (int nt = 0; nt < 16; nt++) {
                float2 b = *reinterpret_cast<const float2*>(
                    B + ks * 4096 + (nt * 8 + ly) * 32 + lx * 8);
                uint32_t b0 = __float_as_uint(b.x);
                uint32_t b1 = __float_as_uint(b.y);
                asm volatile(
                    "mma.sync.aligned.m16n8k8.row.col.f32.tf32.tf32.f32 "
                    "{%0,%1,%2,%3}, {%4,%5,%6,%7}, {%8,%9}, {%0,%1,%2,%3};"
                    : "+f"(acc[nt][0]), "+f"(acc[nt][1]),
                      "+f"(acc[nt][2]), "+f"(acc[nt][3])
                    : "r"(a0), "r"(a1), "r"(a2), "r"(a3), "r"(b0), "r"(b1));
            }
        }
        buf ^= 1;
    }
    __syncthreads();

    const int nc = lane * 4;
    const float4 gg  = *reinterpret_cast<const float4*>(gamma + nc);
    const float4 bbv = *reinterpret_cast<const float4*>(beta + nc);

#pragma unroll 1
    for (int p = 0; p < 2; p++) {
        if ((w >> 2) == p) {
            const int lbase = (w & 3) * 16;
#pragma unroll
            for (int nt = 0; nt < 16; nt++) {
                *reinterpret_cast<float2*>(&sm.C[lbase + ly][nt * 8 + 2 * lx]) =
                    make_float2(acc[nt][0], acc[nt][1]);
                *reinterpret_cast<float2*>(&sm.C[lbase + ly + 8][nt * 8 + 2 * lx]) =
                    make_float2(acc[nt][2], acc[nt][3]);
            }
        }
        __syncthreads();
#pragma unroll 1
        for (int rr = 0; rr < 8; rr++) {
            const int lr   = w * 8 + rr;
            const int gm   = bm + p * 64 + lr;
            const int node = gm % NNODE;
            float4 cv  = *reinterpret_cast<const float4*>(&sm.C[lr][nc]);
            float4 ctv = *reinterpret_cast<const float4*>(Ct + (size_t)node * 128 + nc);
            float4 hv  = *reinterpret_cast<const float4*>(H + (size_t)gm * 128 + nc);
            float x0 = hv.x + fmaxf(cv.x + ctv.x, 0.f);
            float x1 = hv.y + fmaxf(cv.y + ctv.y, 0.f);
            float x2 = hv.z + fmaxf(cv.z + ctv.z, 0.f);
            float x3 = hv.w + fmaxf(cv.w + ctv.w, 0.f);

            float s = x0 + x1 + x2 + x3;
#pragma unroll
            for (int o = 16; o > 0; o >>= 1) s += __shfl_xor_sync(0xffffffffu, s, o);
            float mu = s * (1.f / 128.f);

            float d0 = x0 - mu, d1 = x1 - mu, d2 = x2 - mu, d3 = x3 - mu;
            float q = d0 * d0 + d1 * d1 + d2 * d2 + d3 * d3;
#pragma unroll
            for (int o = 16; o > 0; o >>= 1) q += __shfl_xor_sync(0xffffffffu, q, o);
            float rstd = rsqrtf(q * (1.f / 128.f) + 1e-5f);

            float4 ov;
            ov.x = d0 * rstd * gg.x + bbv.x;
            ov.y = d1 * rstd * gg.y + bbv.y;
            ov.z = d2 * rstd * gg.z + bbv.z;
            ov.w = d3 * rstd * gg.w + bbv.w;
            *reinterpret_cast<float4*>(out + (size_t)gm * 128 + nc) = ov;
            if (outh) {
                __half2 h0 = __floats2half2_rn(ov.x, ov.y);
                __half2 h1 = __floats2half2_rn(ov.z, ov.w);
                *reinterpret_cast<uint2*>(outh + (size_t)gm * 64 + lane * 2) =
                    make_uint2(*reinterpret_cast<uint32_t*>(&h0),
                               *reinterpret_cast<uint32_t*>(&h1));
            }
        }
        __syncthreads();
    }
}

// ---------------- CSR build --------------------------------------------------
__global__ void zero_deg_kernel(int* __restrict__ deg)
{
    int i = blockIdx.x * blockDim.x + threadIdx.x;
    if (i < NNODE) deg[i] = 0;
}

__global__ void hist_kernel(const int* __restrict__ ei0,
                            const int* __restrict__ ei1,
                            const int* __restrict__ ei2,
                            int* __restrict__ deg)
{
    int i = blockIdx.x * blockDim.x + threadIdx.x;
    if (i >= NEDGE_TOT) return;
    int r = i / NE, e = i - r * NE;
    const int* ei = (r == 0) ? ei0 : (r == 1) ? ei1 : ei2;
    atomicAdd(deg + ei[NE + e], 1);
}

__global__ __launch_bounds__(256)
void scan_kernel(const int* __restrict__ deg, int* __restrict__ off,
                 int* __restrict__ cursor)
{
    __shared__ int warp_sums[8];
    __shared__ int s_carry;
    const int tid  = threadIdx.x;
    const int lane = tid & 31;
    const int wid  = tid >> 5;
    if (tid == 0) s_carry = 0;
    __syncthreads();

    for (int base = 0; base < NNODE; base += 256) {
        int i = base + tid;
        int x = (i < NNODE) ? deg[i] : 0;
        int v = x;
#pragma unroll
        for (int d = 1; d < 32; d <<= 1) {
            int t = __shfl_up_sync(0xffffffffu, v, d);
            if (lane >= d) v += t;
        }
        if (lane == 31) warp_sums[wid] = v;
        __syncthreads();
        if (wid == 0 && lane < 8) {
            int s = warp_sums[lane];
#pragma unroll
            for (int d = 1; d < 8; d <<= 1) {
                int t = __shfl_up_sync(0x000000ffu, s, d);
                if (lane >= d) s += t;
            }
            warp_sums[lane] = s;
        }
        __syncthreads();
        int add  = (wid > 0) ? warp_sums[wid - 1] : 0;
        int incl = v + add + s_carry;
        if (i < NNODE) { off[i] = incl - x; cursor[i] = incl - x; }
        __syncthreads();
        if (tid == 255) s_carry = incl;
        __syncthreads();
    }
    if (tid == 0) off[NNODE] = s_carry;
}

__global__ void fill_kernel(const int* __restrict__ ei0,
                            const int* __restrict__ ei1,
                            const int* __restrict__ ei2,
                            int* __restrict__ cursor,
                            int2* __restrict__ entries)
{
    int i = blockIdx.x * blockDim.x + threadIdx.x;
    if (i >= NEDGE_TOT) return;
    int r = i / NE, e = i - r * NE;
    const int* ei = (r == 0) ? ei0 : (r == 1) ? ei1 : ei2;
    int src = ei[e];
    int dst = ei[NE + e];
    int pos = atomicAdd(cursor + dst, 1);
    entries[pos] = make_int2(src, (r << 20) | e);
}

// ---------------- per-node stats: counts + edge-attr sums -------------------
__global__ __launch_bounds__(256)
void stats_kernel(const int* __restrict__ off, const int2* __restrict__ entries,
                  const float* __restrict__ ea0, const float* __restrict__ ea1,
                  float* __restrict__ S0, float* __restrict__ S1,
                  float* __restrict__ cnt)
{
    int warp = (blockIdx.x * blockDim.x + threadIdx.x) >> 5;
    int lane = threadIdx.x & 31;
    if (warp >= NNODE) return;
    const int jb = off[warp], je = off[warp + 1];
    float s0 = 0.f, s1 = 0.f;
    int c0 = 0, c1 = 0, c2 = 0;
    for (int j = jb; j < je; j++) {
        int2 m = entries[j];
        int rel = m.y >> 20, e = m.y & 0xFFFFF;
        if (rel == 0)      { c0++; if (lane < 16) s0 += ea0[(size_t)e * 16 + lane]; }
        else if (rel == 1) { c1++; if (lane < 16) s1 += ea1[(size_t)e * 16 + lane]; }
        else               { c2++; }
    }
    if (lane < 16) {
        S0[(size_t)warp * 16 + lane] = s0;
        S1[(size_t)warp * 16 + lane] = s1;
    }
    if (lane == 0) {
        cnt[(size_t)warp * 4 + 0] = (float)c0;
        cnt[(size_t)warp * 4 + 1] = (float)c1;
        cnt[(size_t)warp * 4 + 2] = (float)c2;
    }
}

// ---------------- Cterm: per-node, per-layer constant term ------------------
#define CT_NODES 16
__global__ __launch_bounds__(128)
void cterm_kernel(const float* __restrict__ S0, const float* __restrict__ S1,
                  const float* __restrict__ cnt,
                  const float* __restrict__ node_b, const float* __restrict__ edge_W,
                  const float* __restrict__ edge_b, float* __restrict__ Ct)
{
    const int l   = blockIdx.y;
    const int j   = threadIdx.x;
    __shared__ float eW0[16 * 128];
    __shared__ float eW1[16 * 128];
    __shared__ float nb0[128], nb1[128], nb2[128], eb0[128], eb1[128];
    __shared__ float sS[2][32];

    for (int k = 0; k < 16; k++) {
        eW0[k * 128 + j] = edge_W[((size_t)(l * 2 + 0) * 16 + k) * 128 + j];
        eW1[k * 128 + j] = edge_W[((size_t)(l * 2 + 1) * 16 + k) * 128 + j];
    }
    nb0[j] = node_b[(size_t)(l * 3 + 0) * 128 + j];
    nb1[j] = node_b[(size_t)(l * 3 + 1) * 128 + j];
    nb2[j] = node_b[(size_t)(l * 3 + 2) * 128 + j];
    eb0[j] = edge_b[(size_t)(l * 2 + 0) * 128 + j];
    eb1[j] = edge_b[(size_t)(l * 2 + 1) * 128 + j];
    __syncthreads();

    const int nbase = blockIdx.x * CT_NODES;
    for (int t = 0; t < CT_NODES; t++) {
        int node = nbase + t;
        int buf = t & 1;
        if (j < 16)      sS[buf][j] = S0[(size_t)node * 16 + j];
        else if (j < 32) sS[buf][j] = S1[(size_t)node * 16 + (j - 16)];
        __syncthreads();
        float c0 = cnt[(size_t)node * 4 + 0];
        float c1 = cnt[(size_t)node * 4 + 1];
        float c2 = cnt[(size_t)node * 4 + 2];
        float v = c0 * (nb0[j] + eb0[j]) + c1 * (nb1[j] + eb1[j]) + c2 * nb2[j];
#pragma unroll
        for (int k = 0; k < 16; k++) v = fmaf(sS[buf][k], eW0[k * 128 + j], v);
#pragma unroll
        for (int k = 0; k < 16; k++) v = fmaf(sS[buf][k + 16], eW1[k * 128 + j], v);
        Ct[((size_t)l * NNODE + node) * 128 + j] = v;
        __syncthreads();
    }
}

// ---------------- inproj Hh mirror from fp32 H (for first gather) -----------
// (built directly by sgemm128; nothing extra needed)

// ---------------- gather (fp16 source): G = sum Hh[b,src] (tf32 out) --------
__global__ __launch_bounds__(256)
void gather_kernel(const __half2* __restrict__ Hh, const int* __restrict__ off,
                   const int2* __restrict__ entries, float* __restrict__ G)
{
    int warp = (blockIdx.x * blockDim.x + threadIdx.x) >> 5;
    int lane = threadIdx.x & 31;
    if (warp >= NNODE) return;
    const int node = warp;
    const int jb = off[node], je = off[node + 1];

    float4 a0[BATCH], a1[BATCH], a2[BATCH];
#pragma unroll
    for (int b = 0; b < BATCH; b++) {
        a0[b] = make_float4(0.f, 0.f, 0.f, 0.f);
        a1[b] = make_float4(0.f, 0.f, 0.f, 0.f);
        a2[b] = make_float4(0.f, 0.f, 0.f, 0.f);
    }

    for (int j = jb; j < je; j++) {
        int2 m = entries[j];
        int src = m.x;
        int rel = m.y >> 20;
        const __half2* hb = Hh + (size_t)src * 64 + lane * 2;
        float4 h[BATCH];
#pragma unroll
        for (int b = 0; b < BATCH; b++) {
            uint2 raw = *reinterpret_cast<const uint2*>(hb + (size_t)b * NNODE * 64);
            __half2 p0 = *reinterpret_cast<__half2*>(&raw.x);
            __half2 p1 = *reinterpret_cast<__half2*>(&raw.y);
            float2 f0 = __half22float2(p0);
            float2 f1 = __half22float2(p1);
            h[b] = make_float4(f0.x, f0.y, f1.x, f1.y);
        }
        if (rel == 0) {
#pragma unroll
            for (int b = 0; b < BATCH; b++) {
                a0[b].x += h[b].x; a0[b].y += h[b].y; a0[b].z += h[b].z; a0[b].w += h[b].w;
            }
        } else if (rel == 1) {
#pragma unroll
            for (int b = 0; b < BATCH; b++) {
                a1[b].x += h[b].x; a1[b].y += h[b].y; a1[b].z += h[b].z; a1[b].w += h[b].w;
            }
        } else {
#pragma unroll
            for (int b = 0; b < BATCH; b++) {
                a2[b].x += h[b].x; a2[b].y += h[b].y; a2[b].z += h[b].z; a2[b].w += h[b].w;
            }
        }
    }

#pragma unroll
    for (int b = 0; b < BATCH; b++) {
        float* gb = G + (size_t)(b * NNODE + node) * 384 + lane * 4;
        float4 v0 = make_float4(to_tf32(a0[b].x), to_tf32(a0[b].y), to_tf32(a0[b].z), to_tf32(a0[b].w));
        float4 v1 = make_float4(to_tf32(a1[b].x), to_tf32(a1[b].y), to_tf32(a1[b].z), to_tf32(a1[b].w));
        float4 v2 = make_float4(to_tf32(a2[b].x), to_tf32(a2[b].y), to_tf32(a2[b].z), to_tf32(a2[b].w));
        *reinterpret_cast<float4*>(gb)       = v0;
        *reinterpret_cast<float4*>(gb + 128) = v1;
        *reinterpret_cast<float4*>(gb + 256) = v2;
    }
}

// ---------------- launch -----------------------------------------------------
extern "C" void kernel_launch(void* const* d_in, const int* in_sizes, int n_in,
                              void* d_out, int out_size)
{
    const float* node_feat = (const float*)d_in[0];
    const float* in_W      = (const float*)d_in[1];
    const float* in_b      = (const float*)d_in[2];
    const float* node_W    = (const float*)d_in[3];
    const float* node_b    = (const float*)d_in[4];
    const float* edge_W    = (const float*)d_in[5];
    const float* edge_b    = (const float*)d_in[6];
    const float* ln_g      = (const float*)d_in[7];
    const float* ln_b      = (const float*)d_in[8];
    const float* ea0       = (const float*)d_in[9];
    const float* ea1       = (const float*)d_in[10];
    const int*   ei0       = (const int*)d_in[11];
    const int*   ei1       = (const int*)d_in[12];
    const int*   ei2       = (const int*)d_in[13];
    float* out = (float*)d_out;

    float *H, *G, *Ct, *S0, *S1, *cnt;
    __half2* Hh;
    float2* Wpre;
    int *deg, *off, *cursor;
    int2* entries;
    cudaGetSymbolAddress((void**)&H,       g_H);
    cudaGetSymbolAddress((void**)&Hh,      g_Hh);
    cudaGetSymbolAddress((void**)&G,       g_G);
    cudaGetSymbolAddress((void**)&Ct,      g_Cterm);
    cudaGetSymbolAddress((void**)&Wpre,    g_Wpre);
    cudaGetSymbolAddress((void**)&S0,      g_S0);
    cudaGetSymbolAddress((void**)&S1,      g_S1);
    cudaGetSymbolAddress((void**)&cnt,     g_cnt);
    cudaGetSymbolAddress((void**)&deg,     g_deg);
    cudaGetSymbolAddress((void**)&off,     g_off);
    cudaGetSymbolAddress((void**)&cursor,  g_cursor);
    cudaGetSymbolAddress((void**)&entries, g_entries);

    // CSR + per-node stats + per-layer constant terms + W pre-conversion
    zero_deg_kernel<<<(NNODE + 255) / 256, 256>>>(deg);
    hist_kernel<<<(NEDGE_TOT + 255) / 256, 256>>>(ei0, ei1, ei2, deg);
    scan_kernel<<<1, 256>>>(deg, off, cursor);
    fill_kernel<<<(NEDGE_TOT + 255) / 256, 256>>>(ei0, ei1, ei2, cursor, entries);
    stats_kernel<<<(NNODE * 32 + 255) / 256, 256>>>(off, entries, ea0, ea1, S0, S1, cnt);
    {
        dim3 grid(NNODE / CT_NODES, NL);
        cterm_kernel<<<grid, 128>>>(S0, S1, cnt, node_b, edge_W, edge_b, Ct);
    }
    prep_w_kernel<<<(NL * 24576 + 255) / 256, 256>>>(node_W, Wpre);

    // input projection (fp32 H + fp16 mirror)
    sgemm128<<<(ROWS + 127) / 128, 256>>>(node_feat, in_W, in_b, H, Hh, ROWS, DN, DM, 0);

    for (int l = 0; l < NL; l++) {
        gather_kernel<<<(NNODE * 32 + 255) / 256, 256>>>(Hh, off, entries, G);
        float* dst = (l == NL - 1) ? out : H;
        gemm_ln_tf32<<<ROWS / 128, 256>>>(
            G, Wpre + (size_t)l * 24576, H, Ct + (size_t)l * NNODE * DM,
            ln_g + (size_t)l * DM, ln_b + (size_t)l * DM,
            dst, (l == NL - 1) ? (__half2*)nullptr : Hh);
    }
}

// round 9
// speedup vs baseline: 1.1271x; 1.1271x over previous
#include <cuda_runtime.h>
#include <cuda_fp16.h>
#include <cstdint>

#define BATCH 4
#define NNODE 20000
#define DN 64
#define DM 128
#define NE 160000
#define NL 2
#define ROWS (BATCH*NNODE)   // 80000
#define NEDGE_TOT (3*NE)     // 480000

// ---------------- scratch (device globals) ----------------------------------
__device__ float   g_H[(size_t)ROWS * DM];            // 41 MB
__device__ __half  g_G[(size_t)ROWS * 3 * DM];        // 61.5 MB (fp16)
__device__ float   g_Cterm[(size_t)NL * NNODE * DM];  // 20.5 MB
__device__ uint2   g_Wpre[(size_t)NL * 12288];        // fp16 B-fragment images
__device__ float   g_S0[(size_t)NNODE * 16];
__device__ float   g_S1[(size_t)NNODE * 16];
__device__ float   g_cnt[(size_t)NNODE * 4];
__device__ int     g_deg[NNODE];
__device__ int     g_off[NNODE + 1];
__device__ int     g_cursor[NNODE];
__device__ int2    g_entries[NEDGE_TOT];

__device__ __forceinline__ void cp16(void* dst, const void* src) {
    uint32_t d = (uint32_t)__cvta_generic_to_shared(dst);
    asm volatile("cp.async.cg.shared.global [%0], [%1], 16;" :: "r"(d), "l"(src));
}
__device__ __forceinline__ void cp_commit() {
    asm volatile("cp.async.commit_group;");
}
__device__ __forceinline__ void cp_wait0() {
    asm volatile("cp.async.wait_group 0;");
}

// ---------------- fp32 SGEMM (inproj only, K=64) -----------------------------
__global__ __launch_bounds__(256)
void sgemm128(const float* __restrict__ A, const float* __restrict__ W,
              const float* __restrict__ bias, float* __restrict__ C,
              int M, int K, int ldc, int coff)
{
    __shared__ float As[2][8][128];
    __shared__ float Bs[2][8][128];
    const int bm  = blockIdx.x * 128;
    const int tid = threadIdx.x;
    const int tx  = tid & 15;
    const int ty  = tid >> 4;

    float acc[8][8];
#pragma unroll
    for (int i = 0; i < 8; i++)
#pragma unroll
        for (int j = 0; j < 8; j++) acc[i][j] = 0.f;

    const int lm  = tid >> 1;
    const int lk4 = (tid & 1) * 4;
    const int lkB = tid >> 5;
    const int lnB = (tid & 31) * 4;
    const bool arow_ok = (bm + lm) < M;
    const float* Aptr = A + (size_t)(bm + lm) * K + lk4;

    float4 av = make_float4(0.f, 0.f, 0.f, 0.f);
    if (arow_ok) av = *reinterpret_cast<const float4*>(Aptr);
    float4 bv = *reinterpret_cast<const float4*>(W + (size_t)lkB * 128 + lnB);
    As[0][lk4 + 0][lm] = av.x; As[0][lk4 + 1][lm] = av.y;
    As[0][lk4 + 2][lm] = av.z; As[0][lk4 + 3][lm] = av.w;
    *reinterpret_cast<float4*>(&Bs[0][lkB][lnB]) = bv;
    __syncthreads();

    int cur = 0;
    for (int k0 = 8; k0 < K; k0 += 8) {
        av = make_float4(0.f, 0.f, 0.f, 0.f);
        if (arow_ok) av = *reinterpret_cast<const float4*>(Aptr + k0);
        bv = *reinterpret_cast<const float4*>(W + (size_t)(k0 + lkB) * 128 + lnB);
#pragma unroll
        for (int kk = 0; kk < 8; kk++) {
            float a[8], b[8];
#pragma unroll
            for (int i = 0; i < 8; i++) a[i] = As[cur][kk][ty * 8 + i];
#pragma unroll
            for (int j = 0; j < 8; j++) b[j] = Bs[cur][kk][tx * 8 + j];
#pragma unroll
            for (int i = 0; i < 8; i++)
#pragma unroll
                for (int j = 0; j < 8; j++)
                    acc[i][j] = fmaf(a[i], b[j], acc[i][j]);
        }
        int nxt = cur ^ 1;
        As[nxt][lk4 + 0][lm] = av.x; As[nxt][lk4 + 1][lm] = av.y;
        As[nxt][lk4 + 2][lm] = av.z; As[nxt][lk4 + 3][lm] = av.w;
        *reinterpret_cast<float4*>(&Bs[nxt][lkB][lnB]) = bv;
        __syncthreads();
        cur = nxt;
    }
#pragma unroll
    for (int kk = 0; kk < 8; kk++) {
        float a[8], b[8];
#pragma unroll
        for (int i = 0; i < 8; i++) a[i] = As[cur][kk][ty * 8 + i];
#pragma unroll
        for (int j = 0; j < 8; j++) b[j] = Bs[cur][kk][tx * 8 + j];
#pragma unroll
        for (int i = 0; i < 8; i++)
#pragma unroll
            for (int j = 0; j < 8; j++)
                acc[i][j] = fmaf(a[i], b[j], acc[i][j]);
    }
#pragma unroll
    for (int i = 0; i < 8; i++) {
        int gm = bm + ty * 8 + i;
        if (gm < M) {
#pragma unroll
            for (int j = 0; j < 8; j += 4) {
                int n = tx * 8 + j;
                float4 o;
                o.x = acc[i][j + 0] + bias[n + 0];
                o.y = acc[i][j + 1] + bias[n + 1];
                o.z = acc[i][j + 2] + bias[n + 2];
                o.w = acc[i][j + 3] + bias[n + 3];
                *reinterpret_cast<float4*>(C + (size_t)gm * ldc + coff + n) = o;
            }
        }
    }
}

// ---------------- W pre-conversion to fp16 B-fragment images -----------------
// layer-flat uint2 index: ch*512 + n*4 + lx
//   .x = pack(W[k0][n],   W[k0+1][n]),  .y = pack(W[k0+8][n], W[k0+9][n])
//   k0 = ch*16 + 2*lx
__global__ void prep_w_kernel(const float* __restrict__ node_W,
                              uint2* __restrict__ Wpre)
{
    int idx = blockIdx.x * blockDim.x + threadIdx.x;
    if (idx >= NL * 12288) return;
    int l  = idx / 12288;
    int r  = idx % 12288;
    int ch = r >> 9;
    int n  = (r >> 2) & 127;
    int lx = r & 3;
    int k0 = ch * 16 + 2 * lx;
    const float* W = node_W + (size_t)l * 3 * DM * DM;   // [384][128]
    __half2 lo = __floats2half2_rn(W[(size_t)k0 * 128 + n],       W[(size_t)(k0 + 1) * 128 + n]);
    __half2 hi = __floats2half2_rn(W[(size_t)(k0 + 8) * 128 + n], W[(size_t)(k0 + 9) * 128 + n]);
    uint2 v;
    v.x = *reinterpret_cast<uint32_t*>(&lo);
    v.y = *reinterpret_cast<uint32_t*>(&hi);
    Wpre[idx] = v;
}

// ---------------- fp16 tensor-core fused GEMM + Cterm + relu + H + LN -------
// out[row] = LN( H[row] + relu( G[row,0:384] @ W[384x128] + Ct[row%NNODE] ) )
// mma.m16n8k16.f16 with fp32 accum; cp.async double-buffered.
__global__ __launch_bounds__(256)
void gemm_ln_f16(const __half* __restrict__ G, const uint2* __restrict__ Wpre,
                 const float* __restrict__ H, const float* __restrict__ Ct,
                 const float* __restrict__ gamma, const float* __restrict__ beta,
                 float* __restrict__ out)
{
    // per buffer: A = 128 rows x 48 B (32 data + 16 pad) = 6144 B
    //             B = 128 n x 32 B (4 lx uint2)          = 4096 B
    __shared__ union SmemU {
        char  raw[2][10240];
        float C[64][132];
    } sm;

    const int tid  = threadIdx.x;
    const int bm   = blockIdx.x * 128;
    const int w    = tid >> 5;
    const int lane = tid & 31;
    const int ly   = lane >> 2;
    const int lx   = lane & 3;

    const int arow = tid >> 1;
    const int aseg = tid & 1;
    const char* Arow = reinterpret_cast<const char*>(G + (size_t)(bm + arow) * 384) + aseg * 16;
    const char* Wp   = reinterpret_cast<const char*>(Wpre);

    float acc[16][4];
#pragma unroll
    for (int nt = 0; nt < 16; nt++)
#pragma unroll
        for (int j = 0; j < 4; j++) acc[nt][j] = 0.f;

    auto stage = [&](int s, int ch) {
        cp16(sm.raw[s] + arow * 48 + aseg * 16, Arow + ch * 32);
        cp16(sm.raw[s] + 6144 + tid * 16,       Wp + (size_t)ch * 4096 + tid * 16);
    };

    stage(0, 0);
    cp_commit();

    int buf = 0;
#pragma unroll 1
    for (int ch = 0; ch < 24; ch++) {
        cp_wait0();
        __syncthreads();
        if (ch + 1 < 24) { stage(buf ^ 1, ch + 1); cp_commit(); }

        const char* A = sm.raw[buf];
        const char* B = sm.raw[buf] + 6144;
        uint32_t a0 = *reinterpret_cast<const uint32_t*>(A + (w * 16 + ly) * 48 + lx * 4);
        uint32_t a1 = *reinterpret_cast<const uint32_t*>(A + (w * 16 + ly + 8) * 48 + lx * 4);
        uint32_t a2 = *reinterpret_cast<const uint32_t*>(A + (w * 16 + ly) * 48 + 16 + lx * 4);
        uint32_t a3 = *reinterpret_cast<const uint32_t*>(A + (w * 16 + ly + 8) * 48 + 16 + lx * 4);
#pragma unroll
        for (int nt = 0; nt < 16; nt++) {
            uint2 b = *reinterpret_cast<const uint2*>(B + (nt * 8 + ly) * 32 + lx * 8);
            asm volatile(
                "mma.sync.aligned.m16n8k16.row.col.f32.f16.f16.f32 "
                "{%0,%1,%2,%3}, {%4,%5,%6,%7}, {%8,%9}, {%0,%1,%2,%3};"
                : "+f"(acc[nt][0]), "+f"(acc[nt][1]),
                  "+f"(acc[nt][2]), "+f"(acc[nt][3])
                : "r"(a0), "r"(a1), "r"(a2), "r"(a3), "r"(b.x), "r"(b.y));
        }
        buf ^= 1;
    }
    __syncthreads();   // staging smem no longer read; safe to overwrite with C

    // ---- epilogue: two 64-row passes through smem, warp-per-row LN ---------
    const int nc = lane * 4;
    const float4 gg  = *reinterpret_cast<const float4*>(gamma + nc);
    const float4 bbv = *reinterpret_cast<const float4*>(beta + nc);

#pragma unroll 1
    for (int p = 0; p < 2; p++) {
        if ((w >> 2) == p) {
            const int lbase = (w & 3) * 16;
#pragma unroll
            for (int nt = 0; nt < 16; nt++) {
                *reinterpret_cast<float2*>(&sm.C[lbase + ly][nt * 8 + 2 * lx]) =
                    make_float2(acc[nt][0], acc[nt][1]);
                *reinterpret_cast<float2*>(&sm.C[lbase + ly + 8][nt * 8 + 2 * lx]) =
                    make_float2(acc[nt][2], acc[nt][3]);
            }
        }
        __syncthreads();
#pragma unroll 1
        for (int rr = 0; rr < 8; rr++) {
            const int lr   = w * 8 + rr;
            const int gm   = bm + p * 64 + lr;
            const int node = gm % NNODE;
            float4 cv  = *reinterpret_cast<const float4*>(&sm.C[lr][nc]);
            float4 ctv = *reinterpret_cast<const float4*>(Ct + (size_t)node * 128 + nc);
            float4 hv  = *reinterpret_cast<const float4*>(H + (size_t)gm * 128 + nc);
            float x0 = hv.x + fmaxf(cv.x + ctv.x, 0.f);
            float x1 = hv.y + fmaxf(cv.y + ctv.y, 0.f);
            float x2 = hv.z + fmaxf(cv.z + ctv.z, 0.f);
            float x3 = hv.w + fmaxf(cv.w + ctv.w, 0.f);

            float s = x0 + x1 + x2 + x3;
#pragma unroll
            for (int o = 16; o > 0; o >>= 1) s += __shfl_xor_sync(0xffffffffu, s, o);
            float mu = s * (1.f / 128.f);

            float d0 = x0 - mu, d1 = x1 - mu, d2 = x2 - mu, d3 = x3 - mu;
            float q = d0 * d0 + d1 * d1 + d2 * d2 + d3 * d3;
#pragma unroll
            for (int o = 16; o > 0; o >>= 1) q += __shfl_xor_sync(0xffffffffu, q, o);
            float rstd = rsqrtf(q * (1.f / 128.f) + 1e-5f);

            float4 ov;
            ov.x = d0 * rstd * gg.x + bbv.x;
            ov.y = d1 * rstd * gg.y + bbv.y;
            ov.z = d2 * rstd * gg.z + bbv.z;
            ov.w = d3 * rstd * gg.w + bbv.w;
            *reinterpret_cast<float4*>(out + (size_t)gm * 128 + nc) = ov;
        }
        __syncthreads();
    }
}

// ---------------- CSR build --------------------------------------------------
__global__ void zero_deg_kernel(int* __restrict__ deg)
{
    int i = blockIdx.x * blockDim.x + threadIdx.x;
    if (i < NNODE) deg[i] = 0;
}

__global__ void hist_kernel(const int* __restrict__ ei0,
                            const int* __restrict__ ei1,
                            const int* __restrict__ ei2,
                            int* __restrict__ deg)
{
    int i = blockIdx.x * blockDim.x + threadIdx.x;
    if (i >= NEDGE_TOT) return;
    int r = i / NE, e = i - r * NE;
    const int* ei = (r == 0) ? ei0 : (r == 1) ? ei1 : ei2;
    atomicAdd(deg + ei[NE + e], 1);
}

__global__ __launch_bounds__(256)
void scan_kernel(const int* __restrict__ deg, int* __restrict__ off,
                 int* __restrict__ cursor)
{
    __shared__ int warp_sums[8];
    __shared__ int s_carry;
    const int tid  = threadIdx.x;
    const int lane = tid & 31;
    const int wid  = tid >> 5;
    if (tid == 0) s_carry = 0;
    __syncthreads();

    for (int base = 0; base < NNODE; base += 256) {
        int i = base + tid;
        int x = (i < NNODE) ? deg[i] : 0;
        int v = x;
#pragma unroll
        for (int d = 1; d < 32; d <<= 1) {
            int t = __shfl_up_sync(0xffffffffu, v, d);
            if (lane >= d) v += t;
        }
        if (lane == 31) warp_sums[wid] = v;
        __syncthreads();
        if (wid == 0 && lane < 8) {
            int s = warp_sums[lane];
#pragma unroll
            for (int d = 1; d < 8; d <<= 1) {
                int t = __shfl_up_sync(0x000000ffu, s, d);
                if (lane >= d) s += t;
            }
            warp_sums[lane] = s;
        }
        __syncthreads();
        int add  = (wid > 0) ? warp_sums[wid - 1] : 0;
        int incl = v + add + s_carry;
        if (i < NNODE) { off[i] = incl - x; cursor[i] = incl - x; }
        __syncthreads();
        if (tid == 255) s_carry = incl;
        __syncthreads();
    }
    if (tid == 0) off[NNODE] = s_carry;
}

__global__ void fill_kernel(const int* __restrict__ ei0,
                            const int* __restrict__ ei1,
                            const int* __restrict__ ei2,
                            int* __restrict__ cursor,
                            int2* __restrict__ entries)
{
    int i = blockIdx.x * blockDim.x + threadIdx.x;
    if (i >= NEDGE_TOT) return;
    int r = i / NE, e = i - r * NE;
    const int* ei = (r == 0) ? ei0 : (r == 1) ? ei1 : ei2;
    int src = ei[e];
    int dst = ei[NE + e];
    int pos = atomicAdd(cursor + dst, 1);
    entries[pos] = make_int2(src, (r << 20) | e);
}

// ---------------- per-node stats: counts + edge-attr sums -------------------
__global__ __launch_bounds__(256)
void stats_kernel(const int* __restrict__ off, const int2* __restrict__ entries,
                  const float* __restrict__ ea0, const float* __restrict__ ea1,
                  float* __restrict__ S0, float* __restrict__ S1,
                  float* __restrict__ cnt)
{
    int warp = (blockIdx.x * blockDim.x + threadIdx.x) >> 5;
    int lane = threadIdx.x & 31;
    if (warp >= NNODE) return;
    const int jb = off[warp], je = off[warp + 1];
    float s0 = 0.f, s1 = 0.f;
    int c0 = 0, c1 = 0, c2 = 0;
    for (int j = jb; j < je; j++) {
        int2 m = entries[j];
        int rel = m.y >> 20, e = m.y & 0xFFFFF;
        if (rel == 0)      { c0++; if (lane < 16) s0 += ea0[(size_t)e * 16 + lane]; }
        else if (rel == 1) { c1++; if (lane < 16) s1 += ea1[(size_t)e * 16 + lane]; }
        else               { c2++; }
    }
    if (lane < 16) {
        S0[(size_t)warp * 16 + lane] = s0;
        S1[(size_t)warp * 16 + lane] = s1;
    }
    if (lane == 0) {
        cnt[(size_t)warp * 4 + 0] = (float)c0;
        cnt[(size_t)warp * 4 + 1] = (float)c1;
        cnt[(size_t)warp * 4 + 2] = (float)c2;
    }
}

// ---------------- Cterm: per-node, per-layer constant term ------------------
#define CT_NODES 16
__global__ __launch_bounds__(128)
void cterm_kernel(const float* __restrict__ S0, const float* __restrict__ S1,
                  const float* __restrict__ cnt,
                  const float* __restrict__ node_b, const float* __restrict__ edge_W,
                  const float* __restrict__ edge_b, float* __restrict__ Ct)
{
    const int l   = blockIdx.y;
    const int j   = threadIdx.x;
    __shared__ float eW0[16 * 128];
    __shared__ float eW1[16 * 128];
    __shared__ float nb0[128], nb1[128], nb2[128], eb0[128], eb1[128];
    __shared__ float sS[2][32];

    for (int k = 0; k < 16; k++) {
        eW0[k * 128 + j] = edge_W[((size_t)(l * 2 + 0) * 16 + k) * 128 + j];
        eW1[k * 128 + j] = edge_W[((size_t)(l * 2 + 1) * 16 + k) * 128 + j];
    }
    nb0[j] = node_b[(size_t)(l * 3 + 0) * 128 + j];
    nb1[j] = node_b[(size_t)(l * 3 + 1) * 128 + j];
    nb2[j] = node_b[(size_t)(l * 3 + 2) * 128 + j];
    eb0[j] = edge_b[(size_t)(l * 2 + 0) * 128 + j];
    eb1[j] = edge_b[(size_t)(l * 2 + 1) * 128 + j];
    __syncthreads();

    const int nbase = blockIdx.x * CT_NODES;
    for (int t = 0; t < CT_NODES; t++) {
        int node = nbase + t;
        int buf = t & 1;
        if (j < 16)      sS[buf][j] = S0[(size_t)node * 16 + j];
        else if (j < 32) sS[buf][j] = S1[(size_t)node * 16 + (j - 16)];
        __syncthreads();
        float c0 = cnt[(size_t)node * 4 + 0];
        float c1 = cnt[(size_t)node * 4 + 1];
        float c2 = cnt[(size_t)node * 4 + 2];
        float v = c0 * (nb0[j] + eb0[j]) + c1 * (nb1[j] + eb1[j]) + c2 * nb2[j];
#pragma unroll
        for (int k = 0; k < 16; k++) v = fmaf(sS[buf][k], eW0[k * 128 + j], v);
#pragma unroll
        for (int k = 0; k < 16; k++) v = fmaf(sS[buf][k + 16], eW1[k * 128 + j], v);
        Ct[((size_t)l * NNODE + node) * 128 + j] = v;
        __syncthreads();
    }
}

// ---------------- gather: G[b,node,r*128:...] = sum H[b,src], fp16 out ------
__global__ __launch_bounds__(256)
void gather_kernel(const float* __restrict__ H, const int* __restrict__ off,
                   const int2* __restrict__ entries, __half* __restrict__ G)
{
    int warp = (blockIdx.x * blockDim.x + threadIdx.x) >> 5;
    int lane = threadIdx.x & 31;
    if (warp >= NNODE) return;
    const int node = warp;
    const int jb = off[node], je = off[node + 1];

    float4 a0[BATCH], a1[BATCH], a2[BATCH];
#pragma unroll
    for (int b = 0; b < BATCH; b++) {
        a0[b] = make_float4(0.f, 0.f, 0.f, 0.f);
        a1[b] = make_float4(0.f, 0.f, 0.f, 0.f);
        a2[b] = make_float4(0.f, 0.f, 0.f, 0.f);
    }

    for (int j = jb; j < je; j++) {
        int2 m = entries[j];
        int src = m.x;
        int rel = m.y >> 20;
        const float* hb = H + (size_t)src * 128 + lane * 4;
        float4 h[BATCH];
#pragma unroll
        for (int b = 0; b < BATCH; b++)
            h[b] = *reinterpret_cast<const float4*>(hb + (size_t)b * NNODE * 128);
        if (rel == 0) {
#pragma unroll
            for (int b = 0; b < BATCH; b++) {
                a0[b].x += h[b].x; a0[b].y += h[b].y; a0[b].z += h[b].z; a0[b].w += h[b].w;
            }
        } else if (rel == 1) {
#pragma unroll
            for (int b = 0; b < BATCH; b++) {
                a1[b].x += h[b].x; a1[b].y += h[b].y; a1[b].z += h[b].z; a1[b].w += h[b].w;
            }
        } else {
#pragma unroll
            for (int b = 0; b < BATCH; b++) {
                a2[b].x += h[b].x; a2[b].y += h[b].y; a2[b].z += h[b].z; a2[b].w += h[b].w;
            }
        }
    }

#pragma unroll
    for (int b = 0; b < BATCH; b++) {
        __half* gb = G + (size_t)(b * NNODE + node) * 384 + lane * 4;
        __half2 p0, p1;
        uint2 v;
        p0 = __floats2half2_rn(a0[b].x, a0[b].y);
        p1 = __floats2half2_rn(a0[b].z, a0[b].w);
        v.x = *reinterpret_cast<uint32_t*>(&p0);
        v.y = *reinterpret_cast<uint32_t*>(&p1);
        *reinterpret_cast<uint2*>(gb) = v;
        p0 = __floats2half2_rn(a1[b].x, a1[b].y);
        p1 = __floats2half2_rn(a1[b].z, a1[b].w);
        v.x = *reinterpret_cast<uint32_t*>(&p0);
        v.y = *reinterpret_cast<uint32_t*>(&p1);
        *reinterpret_cast<uint2*>(gb + 128) = v;
        p0 = __floats2half2_rn(a2[b].x, a2[b].y);
        p1 = __floats2half2_rn(a2[b].z, a2[b].w);
        v.x = *reinterpret_cast<uint32_t*>(&p0);
        v.y = *reinterpret_cast<uint32_t*>(&p1);
        *reinterpret_cast<uint2*>(gb + 256) = v;
    }
}

// ---------------- launch -----------------------------------------------------
extern "C" void kernel_launch(void* const* d_in, const int* in_sizes, int n_in,
                              void* d_out, int out_size)
{
    const float* node_feat = (const float*)d_in[0];
    const float* in_W      = (const float*)d_in[1];
    const float* in_b      = (const float*)d_in[2];
    const float* node_W    = (const float*)d_in[3];
    const float* node_b    = (const float*)d_in[4];
    const float* edge_W    = (const float*)d_in[5];
    const float* edge_b    = (const float*)d_in[6];
    const float* ln_g      = (const float*)d_in[7];
    const float* ln_b      = (const float*)d_in[8];
    const float* ea0       = (const float*)d_in[9];
    const float* ea1       = (const float*)d_in[10];
    const int*   ei0       = (const int*)d_in[11];
    const int*   ei1       = (const int*)d_in[12];
    const int*   ei2       = (const int*)d_in[13];
    float* out = (float*)d_out;

    float *H, *Ct, *S0, *S1, *cnt;
    __half* G;
    uint2* Wpre;
    int *deg, *off, *cursor;
    int2* entries;
    cudaGetSymbolAddress((void**)&H,       g_H);
    cudaGetSymbolAddress((void**)&G,       g_G);
    cudaGetSymbolAddress((void**)&Ct,      g_Cterm);
    cudaGetSymbolAddress((void**)&Wpre,    g_Wpre);
    cudaGetSymbolAddress((void**)&S0,      g_S0);
    cudaGetSymbolAddress((void**)&S1,      g_S1);
    cudaGetSymbolAddress((void**)&cnt,     g_cnt);
    cudaGetSymbolAddress((void**)&deg,     g_deg);
    cudaGetSymbolAddress((void**)&off,     g_off);
    cudaGetSymbolAddress((void**)&cursor,  g_cursor);
    cudaGetSymbolAddress((void**)&entries, g_entries);

    // CSR + per-node stats + per-layer constant terms + W pre-conversion
    zero_deg_kernel<<<(NNODE + 255) / 256, 256>>>(deg);
    hist_kernel<<<(NEDGE_TOT + 255) / 256, 256>>>(ei0, ei1, ei2, deg);
    scan_kernel<<<1, 256>>>(deg, off, cursor);
    fill_kernel<<<(NEDGE_TOT + 255) / 256, 256>>>(ei0, ei1, ei2, cursor, entries);
    stats_kernel<<<(NNODE * 32 + 255) / 256, 256>>>(off, entries, ea0, ea1, S0, S1, cnt);
    {
        dim3 grid(NNODE / CT_NODES, NL);
        cterm_kernel<<<grid, 128>>>(S0, S1, cnt, node_b, edge_W, edge_b, Ct);
    }
    prep_w_kernel<<<(NL * 12288 + 255) / 256, 256>>>(node_W, Wpre);

    // input projection (fp32 for accurate base H)
    sgemm128<<<(ROWS + 127) / 128, 256>>>(node_feat, in_W, in_b, H, ROWS, DN, DM, 0);

    for (int l = 0; l < NL; l++) {
        gather_kernel<<<(NNODE * 32 + 255) / 256, 256>>>(H, off, entries, G);
        float* dst = (l == NL - 1) ? out : H;
        gemm_ln_f16<<<ROWS / 128, 256>>>(
            G, Wpre + (size_t)l * 12288, H, Ct + (size_t)l * NNODE * DM,
            ln_g + (size_t)l * DM, ln_b + (size_t)l * DM, dst);
    }
}